// round 17
// baseline (speedup 1.0000x reference)
#include <cuda_runtime.h>

// LogLinearAttention — algebraic collapse (exact; rel_err=0 every round):
//   softmax over axis=1 then sum over axis=1 => attention columns sum to 1:
//     out[b] = sigmoid( xsum[b,:]·c + S*(br·Wl) + bl )
//   xsum[b,e] = sum_s x[b,s,e],  c[e] = sum_d Wl[d]*Wr[d,e].  q/v dead.
//
// R14: xsum-FIRST ordering — nothing precedes the big x stream. K1 is the
// validated 296-block streaming loop writing partial xsum vectors (no c
// dependency). K2 (128 one-wave blocks) builds c slices directly from Wr
// (c never materializes; k_c eliminated) and dots with the folded xsum.
// K3 is the validated finisher. No cross-block sync anywhere.

#define BB 8
#define SS 2048
#define DD 512
#define DD4 (DD / 4)              // 128 float4 columns
#define JPB 37                    // row-range blocks per batch
#define NBLK (BB * JPB)           // 296 = 2 * 148 streaming blocks
#define VPB (2 * JPB)             // 74 partial vectors per batch
#define DPB 16                    // dot blocks per batch (d-chunks)
#define DCH (DD / DPB)            // 32 d rows per dot block

__device__ float g_xp[NBLK * 2 * DD];   // partial xsum vectors (1.2 MB)
__device__ float g_dots[BB * DPB];      // per-block partial dot scalars

// ── K1: pure x stream, validated loop shape, zero prologue ──
__global__ void __launch_bounds__(256) k_xsum(
    const float* __restrict__ x)
{
    const int blk = blockIdx.x;
    const int b   = blk / JPB;
    const int j   = blk % JPB;
    const int tid = threadIdx.x;
    const int col = tid & (DD4 - 1);          // float4 column 0..127
    const int r0  = tid >> 7;                 // 0 or 1

    const int r_begin = (j * SS) / JPB;
    const int r_end   = ((j + 1) * SS) / JPB;
    const float4* xb  = reinterpret_cast<const float4*>(x + (size_t)b * SS * DD);

    float4 acc = make_float4(0.f, 0.f, 0.f, 0.f);
    int r = r_begin + r0;
#pragma unroll 4
    for (; r < r_end; r += 2) {               // continuous stream, MLP_p1 ~ 4
        float4 v = xb[(size_t)r * DD4 + col];
        acc.x += v.x; acc.y += v.y; acc.z += v.z; acc.w += v.w;
    }
    // vector id = (b*37 + j)*2 + r0 : contiguous 74 vectors per batch
    reinterpret_cast<float4*>(g_xp)[((size_t)blk * 2 + r0) * DD4 + col] = acc;
}

// ── K2: 128 one-wave blocks. Block (b, i): fold 74 xsum partials, build the
//    i-th 32-row slice of c from Wr/Wl directly, dot, reduce → scalar. ──
__global__ void __launch_bounds__(128) k_dot(
    const float* __restrict__ Wr,
    const float* __restrict__ Wl)
{
    const int b   = blockIdx.x / DPB;
    const int i   = blockIdx.x % DPB;
    const int tid = threadIdx.x;               // one float4 column each

    // fold this batch's 74 xsum partials for this column (L2-hot)
    float4 xs = make_float4(0.f, 0.f, 0.f, 0.f);
    const float4* pp = reinterpret_cast<const float4*>(g_xp) + (size_t)b * VPB * DD4 + tid;
#pragma unroll 8
    for (int p = 0; p < VPB; ++p) {
        float4 v = pp[(size_t)p * DD4];
        xs.x += v.x; xs.y += v.y; xs.z += v.z; xs.w += v.w;
    }

    // build c slice for d in [i*32, i*32+32) at this column (L2-hot Wr)
    float4 cp = make_float4(0.f, 0.f, 0.f, 0.f);
#pragma unroll 8
    for (int k = 0; k < DCH; ++k) {
        const int d = i * DCH + k;
        const float wl = __ldg(&Wl[d]);
        const float4 w = reinterpret_cast<const float4*>(Wr)[(size_t)d * DD4 + tid];
        cp.x += wl * w.x; cp.y += wl * w.y; cp.z += wl * w.z; cp.w += wl * w.w;
    }

    float val = xs.x * cp.x + xs.y * cp.y + xs.z * cp.z + xs.w * cp.w;

#pragma unroll
    for (int off = 16; off > 0; off >>= 1)
        val += __shfl_down_sync(0xffffffffu, val, off);
    __shared__ float warp_s[4];
    if ((tid & 31) == 0) warp_s[tid >> 5] = val;
    __syncthreads();
    if (tid == 0)
        g_dots[blockIdx.x] = warp_s[0] + warp_s[1] + warp_s[2] + warp_s[3];
}

// ── K3: validated finisher — fold 16 scalars per batch + bias, sigmoid ──
__global__ void __launch_bounds__(128) k_final(
    const float* __restrict__ br,
    const float* __restrict__ Wl,
    const float* __restrict__ bl,
    float* __restrict__ out)
{
    const int tid = threadIdx.x;
    __shared__ float warp_s[4];
    __shared__ float s_bias;

    const float4 br4 = reinterpret_cast<const float4*>(br)[tid];
    const float4 wl4 = reinterpret_cast<const float4*>(Wl)[tid];
    float bv = br4.x * wl4.x + br4.y * wl4.y + br4.z * wl4.z + br4.w * wl4.w;
#pragma unroll
    for (int off = 16; off > 0; off >>= 1)
        bv += __shfl_down_sync(0xffffffffu, bv, off);
    if ((tid & 31) == 0) warp_s[tid >> 5] = bv;
    __syncthreads();
    if (tid == 0) s_bias = warp_s[0] + warp_s[1] + warp_s[2] + warp_s[3];
    __syncthreads();

    float d = g_dots[tid];                     // BB*DPB = 128 scalars
#pragma unroll
    for (int off = 8; off > 0; off >>= 1)
        d += __shfl_down_sync(0xffffffffu, d, off, 16);
    if ((tid & 15) == 0) {
        const int b = tid >> 4;
        float z = d + (float)SS * s_bias + bl[0];
        out[b] = 1.0f / (1.0f + expf(-z));
    }
}

extern "C" void kernel_launch(void* const* d_in, const int* in_sizes, int n_in,
                              void* d_out, int out_size)
{
    // metadata order: x, Wq, bq, Wv, bv, Wr, br, Wl, bl
    const float* x  = (const float*)d_in[0];
    const float* Wr = (const float*)d_in[5];
    const float* br = (const float*)d_in[6];
    const float* Wl = (const float*)d_in[7];
    const float* bl = (const float*)d_in[8];
    float* out = (float*)d_out;

    k_xsum<<<NBLK, 256>>>(x);
    k_dot<<<BB * DPB, 128>>>(Wr, Wl);
    k_final<<<1, 128>>>(br, Wl, bl, out);
}